// round 3
// baseline (speedup 1.0000x reference)
#include <cuda_runtime.h>
#include <math.h>

// Problem constants (from reference): B=2, S=2048, D=1024, H=16, HD=64
#define B_  2
#define S_  2048
#define D_  1024
#define H_  16
#define HD_ 64
#define SCALE_ 0.03125f   // D^-0.5 (reference scales by full input dim)

// Scratch (device globals; no dynamic allocation allowed)
__device__ float g_q[(size_t)B_*H_*S_*HD_];     // [B,H,S,HD]
__device__ float g_k[(size_t)B_*H_*S_*HD_];
__device__ float g_v[(size_t)B_*H_*S_*HD_];
__device__ float g_att[(size_t)B_*S_*D_];       // concat heads [B,S,D]

// ---------------------------------------------------------------------------
// Kernel 1: QKV projection.  C[M=B*S, N=3*H*HD] = x[M,K=D] @ Wbig[K,N]
// Each 64-wide n-tile is exactly one (which, head) block (HD=64).
// 64x64x16 tiles, 256 threads, 4x4 microtile per thread.
// ---------------------------------------------------------------------------
__global__ __launch_bounds__(256) void qkv_kernel(
    const float* __restrict__ x,
    const float* __restrict__ Wq,
    const float* __restrict__ Wk,
    const float* __restrict__ Wv)
{
    const int nb = blockIdx.x;          // 0..47  (3 * H)
    const int mb = blockIdx.y;          // 0..63
    const int which = nb >> 4;          // 0=q,1=k,2=v
    const int h = nb & 15;
    const float* W = (which == 0 ? Wq : which == 1 ? Wk : Wv) + (size_t)h * D_ * HD_;
    float* Outb = (which == 0 ? g_q : which == 1 ? g_k : g_v);

    __shared__ float As[16][64];   // [k][m]
    __shared__ float Bs[16][64];   // [k][e]

    const int t  = threadIdx.x;
    const int tx = t & 15, ty = t >> 4;
    const int m0 = mb * 64;

    // load-index precompute
    const int lm  = t >> 2;          // A row within tile (0..63)
    const int lk4 = (t & 3) * 4;     // A k offset (0,4,8,12)
    const int bk  = t >> 4;          // B k row (0..15)
    const int be  = (t & 15) * 4;    // B e offset (0..60)

    float acc[4][4];
    #pragma unroll
    for (int i = 0; i < 4; i++)
        #pragma unroll
        for (int j = 0; j < 4; j++) acc[i][j] = 0.f;

    for (int k0 = 0; k0 < D_; k0 += 16) {
        float4 av = *(const float4*)(x + (size_t)(m0 + lm) * D_ + k0 + lk4);
        float4 bv = *(const float4*)(W + (size_t)(k0 + bk) * HD_ + be);
        As[lk4 + 0][lm] = av.x;
        As[lk4 + 1][lm] = av.y;
        As[lk4 + 2][lm] = av.z;
        As[lk4 + 3][lm] = av.w;
        *(float4*)&Bs[bk][be] = bv;
        __syncthreads();
        #pragma unroll
        for (int k = 0; k < 16; k++) {
            float4 a4 = *(float4*)&As[k][ty * 4];
            float4 b4 = *(float4*)&Bs[k][tx * 4];
            float ar[4] = {a4.x, a4.y, a4.z, a4.w};
            float br[4] = {b4.x, b4.y, b4.z, b4.w};
            #pragma unroll
            for (int i = 0; i < 4; i++)
                #pragma unroll
                for (int j = 0; j < 4; j++)
                    acc[i][j] += ar[i] * br[j];
        }
        __syncthreads();
    }

    // epilogue: scatter into [B,H,S,HD]
    #pragma unroll
    for (int i = 0; i < 4; i++) {
        const int m = m0 + ty * 4 + i;
        const int b = m >> 11;           // / 2048
        const int s = m & 2047;
        float* dst = Outb + (((size_t)(b * H_ + h) * S_ + s) * HD_) + tx * 4;
        float4 o = make_float4(acc[i][0], acc[i][1], acc[i][2], acc[i][3]);
        *(float4*)dst = o;
    }
}

// ---------------------------------------------------------------------------
// Kernel 2: causal flash attention, fp32.
// One block = 64 query rows of one (b,h); 64 threads, 1 query row per thread.
// KV tiles of 64. Online softmax. s[64] & acc[64] live in registers (all
// accesses compile-time indexed); p is round-tripped through the kT smem
// buffer (reused after QK phase) so the PV j-loop can stay rolled.
// ---------------------------------------------------------------------------
__global__ __launch_bounds__(64) void attn_kernel()
{
    const int qt  = blockIdx.x;     // 0..S/64-1
    const int bh  = blockIdx.y;     // 0..B*H-1  (== b*H + h)
    const int row = threadIdx.x;    // 0..63

    const float* Qb = g_q + (size_t)bh * S_ * HD_;
    const float* Kb = g_k + (size_t)bh * S_ * HD_;
    const float* Vb = g_v + (size_t)bh * S_ * HD_;

    __shared__ float q_s[64 * 64];  // [row][d]
    __shared__ float kT [64 * 64];  // [d][j]  (later reused as p[j][row])
    __shared__ float v_s[64 * 64];  // [j][e]

    // load q tile (contiguous 16KB copy)
    {
        const float4* src = (const float4*)(Qb + (size_t)qt * 64 * HD_);
        float4* dst = (float4*)q_s;
        #pragma unroll
        for (int i = 0; i < 16; i++) dst[row + i * 64] = src[row + i * 64];
    }

    float acc[64];
    #pragma unroll
    for (int e = 0; e < 64; e++) acc[e] = 0.f;
    float m_i = -1e30f, l_i = 0.f;

    const int ntiles = qt + 1;
    for (int tile = 0; tile < ntiles; tile++) {
        const int j0 = tile * 64;
        __syncthreads();   // prev PV reads of kT/v_s done; q load visible on iter 0

        // load K tile transposed: thread 'row' owns K row (j0+row)
        {
            const float4* krow = (const float4*)(Kb + (size_t)(j0 + row) * HD_);
            #pragma unroll
            for (int dq = 0; dq < 16; dq++) {
                float4 k4 = krow[dq];
                kT[(dq * 4 + 0) * 64 + row] = k4.x;
                kT[(dq * 4 + 1) * 64 + row] = k4.y;
                kT[(dq * 4 + 2) * 64 + row] = k4.z;
                kT[(dq * 4 + 3) * 64 + row] = k4.w;
            }
            const float4* vsrc = (const float4*)(Vb + (size_t)j0 * HD_);
            float4* vdst = (float4*)v_s;
            #pragma unroll
            for (int i = 0; i < 16; i++) vdst[row + i * 64] = vsrc[row + i * 64];
        }
        __syncthreads();

        // scores: s[j] = q_row . k_j
        float s[64];
        #pragma unroll
        for (int j = 0; j < 64; j++) s[j] = 0.f;
        #pragma unroll 1
        for (int d0 = 0; d0 < 64; d0 += 4) {
            float4 qv = *(float4*)&q_s[row * 64 + d0];
            #pragma unroll
            for (int j = 0; j < 64; j += 4) {
                float4 ka = *(float4*)&kT[(d0 + 0) * 64 + j];
                float4 kb = *(float4*)&kT[(d0 + 1) * 64 + j];
                float4 kc = *(float4*)&kT[(d0 + 2) * 64 + j];
                float4 kd = *(float4*)&kT[(d0 + 3) * 64 + j];
                s[j + 0] += qv.x * ka.x + qv.y * kb.x + qv.z * kc.x + qv.w * kd.x;
                s[j + 1] += qv.x * ka.y + qv.y * kb.y + qv.z * kc.y + qv.w * kd.y;
                s[j + 2] += qv.x * ka.z + qv.y * kb.z + qv.z * kc.z + qv.w * kd.z;
                s[j + 3] += qv.x * ka.w + qv.y * kb.w + qv.z * kc.w + qv.w * kd.w;
            }
        }

        const bool diag = (tile == qt);

        // online softmax update
        float mn = m_i;
        #pragma unroll
        for (int j = 0; j < 64; j++) {
            float tv = s[j] * SCALE_;
            if (diag && j > row) tv = -1e30f;
            s[j] = tv;
            mn = fmaxf(mn, tv);
        }
        const float alpha = __expf(m_i - mn);
        m_i = mn;
        float lsum = 0.f;
        #pragma unroll
        for (int j = 0; j < 64; j++) {
            float p = __expf(s[j] - mn);
            s[j] = p;
            lsum += p;
        }
        l_i = l_i * alpha + lsum;
        #pragma unroll
        for (int e = 0; e < 64; e++) acc[e] *= alpha;

        __syncthreads();   // everyone done reading kT -> safe to reuse for p
        #pragma unroll
        for (int j = 0; j < 64; j++) kT[j * 64 + row] = s[j];  // own writes, own reads

        // PV: acc[e] += p[j] * v[j][e]
        #pragma unroll 1
        for (int j = 0; j < 64; j++) {
            const float pj = kT[j * 64 + row];
            const float* vr = &v_s[j * 64];
            #pragma unroll
            for (int e = 0; e < 64; e += 4) {
                float4 vv = *(float4*)&vr[e];
                acc[e + 0] += pj * vv.x;
                acc[e + 1] += pj * vv.y;
                acc[e + 2] += pj * vv.z;
                acc[e + 3] += pj * vv.w;
            }
        }
    }

    // write normalized output into concat layout [B,S,H*HD]
    const int b = bh >> 4;
    const int h = bh & 15;
    const float inv_l = 1.0f / l_i;
    float* outp = g_att + ((size_t)b * S_ + (size_t)qt * 64 + row) * D_ + h * HD_;
    #pragma unroll
    for (int e = 0; e < 64; e += 4) {
        float4 o = make_float4(acc[e] * inv_l, acc[e + 1] * inv_l,
                               acc[e + 2] * inv_l, acc[e + 3] * inv_l);
        *(float4*)(outp + e) = o;
    }
}

// ---------------------------------------------------------------------------
// Kernel 3: output projection. out[M,N] = g_att[M,K] @ Wp^T + bp
// (out[m][n] = sum_k att[m][k] * Wp[n][k] + bp[n])
// ---------------------------------------------------------------------------
__global__ __launch_bounds__(256) void proj_kernel(
    const float* __restrict__ Wp,
    const float* __restrict__ bp,
    float* __restrict__ out)
{
    const int nb = blockIdx.x;   // 0..15
    const int mb = blockIdx.y;   // 0..63

    __shared__ float As[16][64];  // [k][m]
    __shared__ float Bs[16][64];  // [k][n]

    const int t  = threadIdx.x;
    const int tx = t & 15, ty = t >> 4;
    const int m0 = mb * 64, n0 = nb * 64;

    const int lr = t >> 2;          // A m-row / B n-row within tile
    const int lq = (t & 3) * 4;     // k offset

    float acc[4][4];
    #pragma unroll
    for (int i = 0; i < 4; i++)
        #pragma unroll
        for (int j = 0; j < 4; j++) acc[i][j] = 0.f;

    for (int k0 = 0; k0 < D_; k0 += 16) {
        float4 av = *(const float4*)(g_att + (size_t)(m0 + lr) * D_ + k0 + lq);
        float4 bv = *(const float4*)(Wp   + (size_t)(n0 + lr) * D_ + k0 + lq);
        As[lq + 0][lr] = av.x;
        As[lq + 1][lr] = av.y;
        As[lq + 2][lr] = av.z;
        As[lq + 3][lr] = av.w;
        Bs[lq + 0][lr] = bv.x;
        Bs[lq + 1][lr] = bv.y;
        Bs[lq + 2][lr] = bv.z;
        Bs[lq + 3][lr] = bv.w;
        __syncthreads();
        #pragma unroll
        for (int k = 0; k < 16; k++) {
            float4 a4 = *(float4*)&As[k][ty * 4];
            float4 b4 = *(float4*)&Bs[k][tx * 4];
            float ar[4] = {a4.x, a4.y, a4.z, a4.w};
            float br[4] = {b4.x, b4.y, b4.z, b4.w};
            #pragma unroll
            for (int i = 0; i < 4; i++)
                #pragma unroll
                for (int j = 0; j < 4; j++)
                    acc[i][j] += ar[i] * br[j];
        }
        __syncthreads();
    }

    const float4 bb = *(const float4*)(bp + n0 + tx * 4);
    const float bbr[4] = {bb.x, bb.y, bb.z, bb.w};
    #pragma unroll
    for (int i = 0; i < 4; i++) {
        const int m = m0 + ty * 4 + i;
        float4 o = make_float4(acc[i][0] + bbr[0], acc[i][1] + bbr[1],
                               acc[i][2] + bbr[2], acc[i][3] + bbr[3]);
        *(float4*)(out + (size_t)m * D_ + n0 + tx * 4) = o;
    }
}

// ---------------------------------------------------------------------------
// Launch
// ---------------------------------------------------------------------------
extern "C" void kernel_launch(void* const* d_in, const int* in_sizes, int n_in,
                              void* d_out, int out_size)
{
    const float* x  = (const float*)d_in[0];
    const float* Wq = (const float*)d_in[1];
    const float* Wk = (const float*)d_in[2];
    const float* Wv = (const float*)d_in[3];
    const float* Wp = (const float*)d_in[4];
    const float* bp = (const float*)d_in[5];
    float* out = (float*)d_out;
    (void)in_sizes; (void)n_in; (void)out_size;

    qkv_kernel <<<dim3(3 * H_, (B_ * S_) / 64), 256>>>(x, Wq, Wk, Wv);
    attn_kernel<<<dim3(S_ / 64, B_ * H_),        64>>>();
    proj_kernel<<<dim3(D_ / 64, (B_ * S_) / 64), 256>>>(Wp, bp, out);
}